// round 17
// baseline (speedup 1.0000x reference)
#include <cuda_runtime.h>
#include <cuda_bf16.h>
#include <math.h>
#include <cstdint>

#define BATCH 8
#define CDIM  256
#define TCDIM 512
#define NPIX  2304          // 48*48
#define EPSN  1e-6f
#define SCALE 0.0625f       // 1/sqrt(256)

// ---------------- scratch (device globals: allocation-free) ----------------
__device__ __nv_bfloat16 g_xT [BATCH * NPIX * CDIM];
__device__ __nv_bfloat16 g_tT [BATCH * NPIX * TCDIM];
__device__ __nv_bfloat16 g_Wqb[CDIM * CDIM];
__device__ __nv_bfloat16 g_Wkb[CDIM * TCDIM];
__device__ __nv_bfloat16 g_Wvb[CDIM * TCDIM];
__device__ float         g_qf [BATCH * NPIX * CDIM];
__device__ float         g_kf [BATCH * NPIX * CDIM];
__device__ uint8_t       g_q8 [BATCH * NPIX * CDIM];
__device__ uint8_t       g_k8 [BATCH * NPIX * CDIM];
__device__ __nv_bfloat16 g_vT [BATCH * CDIM * NPIX];

// ======================= PTX helpers =======================================
__device__ __forceinline__ uint32_t smem_u32(const void* p) {
    uint32_t a;
    asm("{ .reg .u64 t; cvta.to.shared.u64 t, %1; cvt.u32.u64 %0, t; }" : "=r"(a) : "l"(p));
    return a;
}
__device__ __forceinline__ float ex2f(float x) {
    float y;
    asm("ex2.approx.f32 %0, %1;" : "=f"(y) : "f"(x));
    return y;
}
__device__ __forceinline__ uint32_t packbf(float lo, float hi) {
    __nv_bfloat162 h = __float22bfloat162_rn(make_float2(lo, hi));
    return *reinterpret_cast<uint32_t*>(&h);
}
__device__ __forceinline__ uint32_t pack_e4m3_4(float f0, float f1, float f2, float f3) {
    uint32_t r;
    asm("{\n\t.reg .b16 l, h;\n\t"
        "cvt.rn.satfinite.e4m3x2.f32 l, %2, %1;\n\t"
        "cvt.rn.satfinite.e4m3x2.f32 h, %4, %3;\n\t"
        "mov.b32 %0, {l, h};\n\t}"
        : "=r"(r) : "f"(f0), "f"(f1), "f"(f2), "f"(f3));
    return r;
}
#define CP_ASYNC16(s, g) \
    asm volatile("cp.async.cg.shared.global [%0], [%1], 16;" :: "r"(s), "l"(g) : "memory")
#define CP_COMMIT()  asm volatile("cp.async.commit_group;" ::: "memory")
#define CP_WAIT2()   asm volatile("cp.async.wait_group 2;" ::: "memory")
#define CP_WAIT1()   asm volatile("cp.async.wait_group 1;" ::: "memory")
#define CP_WAIT0()   asm volatile("cp.async.wait_group 0;" ::: "memory")
#define LDSM_X4(r0, r1, r2, r3, addr) \
    asm volatile("ldmatrix.sync.aligned.m8n8.x4.shared.b16 {%0,%1,%2,%3}, [%4];" \
        : "=r"(r0), "=r"(r1), "=r"(r2), "=r"(r3) : "r"(addr))
#define LDSM_X2(r0, r1, addr) \
    asm volatile("ldmatrix.sync.aligned.m8n8.x2.shared.b16 {%0,%1}, [%2];" \
        : "=r"(r0), "=r"(r1) : "r"(addr))
#define MMA16816(c, a, b) \
    asm volatile("mma.sync.aligned.m16n8k16.row.col.f32.bf16.bf16.f32 " \
        "{%0,%1,%2,%3}, {%4,%5,%6,%7}, {%8,%9}, {%0,%1,%2,%3};" \
        : "+f"((c)[0]), "+f"((c)[1]), "+f"((c)[2]), "+f"((c)[3]) \
        : "r"((a)[0]), "r"((a)[1]), "r"((a)[2]), "r"((a)[3]), "r"((b)[0]), "r"((b)[1]))
#define MMA16816R(c, a0, a1, a2, a3, b0, b1) \
    asm volatile("mma.sync.aligned.m16n8k16.row.col.f32.bf16.bf16.f32 " \
        "{%0,%1,%2,%3}, {%4,%5,%6,%7}, {%8,%9}, {%0,%1,%2,%3};" \
        : "+f"((c)[0]), "+f"((c)[1]), "+f"((c)[2]), "+f"((c)[3]) \
        : "r"(a0), "r"(a1), "r"(a2), "r"(a3), "r"(b0), "r"(b1))
#define MMAFP8(c, a0, a1, a2, a3, b0, b1) \
    asm volatile("mma.sync.aligned.m16n8k32.row.col.f32.e4m3.e4m3.f32 " \
        "{%0,%1,%2,%3}, {%4,%5,%6,%7}, {%8,%9}, {%0,%1,%2,%3};" \
        : "+f"((c)[0]), "+f"((c)[1]), "+f"((c)[2]), "+f"((c)[3]) \
        : "r"(a0), "r"(a1), "r"(a2), "r"(a3), "r"(b0), "r"(b1))

// ===========================================================================
// Fused attention + residual, BR=64 (2 CTAs/SM).
// 8 warps = 4 row-groups x 2 D-halves. S (fp8) duplicated per D-half;
// PV (bf16) split: each warp owns 16 rows x 128 D-cols.
// K double-buffered; V single-buffered (load overlaps S compute).
// ===========================================================================
#define BR    64
#define BC    64
#define NBLK  (NPIX / BC)                 // 36
#define QSTR8 272
#define VSTR  144
#define SM_K0   (BR * QSTR8)              // 17408
#define SM_KB   (BC * QSTR8)              // 17408
#define SM_V0   (SM_K0 + 2 * SM_KB)       // 52224
#define SM_VB   (CDIM * VSTR)             // 36864
#define SM_TOT  (SM_V0 + SM_VB)           // 89088  (epilogue needs 256*72*4=73728)
#define AOSTR 72

__global__ void __launch_bounds__(256, 2)
attn_kernel(const uint8_t* __restrict__ q8,
            const uint8_t* __restrict__ k8,
            const __nv_bfloat16* __restrict__ vT,
            const float* __restrict__ x,
            const float* __restrict__ alpha,
            float* __restrict__ y)
{
    extern __shared__ __align__(128) unsigned char smem[];
    const uint32_t sb = smem_u32(smem);

    const int tid  = threadIdx.x;
    const int lane = tid & 31;
    const int wid  = tid >> 5;
    const int wr   = wid & 3;              // row group (16 rows)
    const int wc   = wid >> 2;             // D half (128 cols)
    const int b    = blockIdx.y;
    const int m0   = blockIdx.x * BR;
    const int gid  = lane >> 2, tig = lane & 3;

    const uint8_t* qg = q8 + ((size_t)b * NPIX + m0) * CDIM;
    const uint8_t* kg = k8 + (size_t)b * NPIX * CDIM;
    const __nv_bfloat16* vg = vT + (size_t)b * CDIM * NPIX;
    const float av = *alpha;

    // ---- prologue: q tile (64 x 256B) + K[0] ----
    {
        const int row = tid >> 2, q4 = tid & 3;
        const uint32_t sq = sb + row * QSTR8;
        const uint8_t* gq = qg + (size_t)row * CDIM;
        const uint32_t sk = sb + SM_K0 + row * QSTR8;
        const uint8_t* gk = kg + (size_t)row * CDIM;
        #pragma unroll
        for (int s = 0; s < 4; s++) {
            const int seg = q4 + 4 * s;
            CP_ASYNC16(sq + seg * 16, gq + seg * 16);
            CP_ASYNC16(sk + seg * 16, gk + seg * 16);
        }
    }
    CP_COMMIT();
    CP_WAIT0();
    __syncthreads();

    auto loadK = [&](int j, int buf) {
        const int row = tid >> 2, q4 = tid & 3;
        const uint32_t sk = sb + SM_K0 + buf * SM_KB + row * QSTR8;
        const uint8_t* gk = kg + (size_t)(j * BC + row) * CDIM;
        #pragma unroll
        for (int s = 0; s < 4; s++) {
            const int seg = q4 + 4 * s;
            CP_ASYNC16(sk + seg * 16, gk + seg * 16);
        }
    };
    auto loadV = [&](int j) {
        const uint32_t sv = sb + SM_V0 + tid * VSTR;
        const __nv_bfloat16* gv = vg + (size_t)tid * NPIX + j * BC;
        #pragma unroll
        for (int s = 0; s < 8; s++)
            CP_ASYNC16(sv + s * 16, gv + s * 8);
    };

    float oacc[16][4];
    #pragma unroll
    for (int i = 0; i < 16; i++)
        #pragma unroll
        for (int e = 0; e < 4; e++) oacc[i][e] = 0.f;
    float l0 = 0.f, l1 = 0.f;

    const uint32_t sqa = sb + (wr * 16 + (lane & 15)) * QSTR8 + (lane >> 4) * 16;
    const int x4row = (lane >> 4) * 8 + (lane & 7);
    const int x4off = ((lane >> 3) & 1) * 16;
    const float C1 = SCALE * 1.44269504f;
    const float C2 = SCALE * 1.44269504f;

    for (int j = 0; j < NBLK; j++) {
        // V[j] (single buffer: all warps past PV[j-1] due to loop-end sync)
        loadV(j);
        CP_COMMIT();
        const bool haveNext = (j + 1 < NBLK);
        if (haveNext) { loadK(j + 1, (j + 1) & 1); CP_COMMIT(); }

        // ---- S = q . k^T  (fp8, K=256, 8 k32 chunks) ----
        float sacc[8][4];
        #pragma unroll
        for (int t = 0; t < 8; t++)
            #pragma unroll
            for (int e = 0; e < 4; e++) sacc[t][e] = 0.f;

        const uint32_t kba = sb + SM_K0 + (j & 1) * SM_KB + x4row * QSTR8 + x4off;
        #pragma unroll
        for (int kc = 0; kc < 8; kc++) {
            uint32_t a0, a1, a2, a3;
            LDSM_X4(a0, a1, a2, a3, sqa + kc * 32);
            #pragma unroll
            for (int np = 0; np < 4; np++) {
                uint32_t b0, b1, b2, b3;
                LDSM_X4(b0, b1, b2, b3, kba + np * 16 * QSTR8 + kc * 32);
                MMAFP8(sacc[2 * np],     a0, a1, a2, a3, b0, b1);
                MMAFP8(sacc[2 * np + 1], a0, a1, a2, a3, b2, b3);
            }
        }

        // ---- exp (fixed shift) + pack ----
        uint32_t pf[8][2];
        #pragma unroll
        for (int t = 0; t < 8; t++) {
            const float e0 = ex2f(fmaf(sacc[t][0], C1, -C2));
            const float e1 = ex2f(fmaf(sacc[t][1], C1, -C2));
            const float e2 = ex2f(fmaf(sacc[t][2], C1, -C2));
            const float e3 = ex2f(fmaf(sacc[t][3], C1, -C2));
            l0 += e0 + e1;
            l1 += e2 + e3;
            pf[t][0] = packbf(e0, e1);
            pf[t][1] = packbf(e2, e3);
        }

        // ---- wait V[j] (K[j+1] may still fly), sync, PV ----
        if (haveNext) { CP_WAIT1(); } else { CP_WAIT0(); }
        __syncthreads();

        const uint32_t vba = sb + SM_V0 + (wc * 128 + x4row) * VSTR + x4off;
        #pragma unroll
        for (int kk = 0; kk < 4; kk++) {
            const uint32_t a0 = pf[2 * kk][0], a1 = pf[2 * kk][1];
            const uint32_t a2 = pf[2 * kk + 1][0], a3 = pf[2 * kk + 1][1];
            #pragma unroll
            for (int np = 0; np < 8; np++) {
                uint32_t b0, b1, b2, b3;
                LDSM_X4(b0, b1, b2, b3, vba + np * 16 * VSTR + kk * 32);
                MMA16816R(oacc[2 * np],     a0, a1, a2, a3, b0, b1);
                MMA16816R(oacc[2 * np + 1], a0, a1, a2, a3, b2, b3);
            }
        }

        // K[j+1] must be resident before next S; V buffer must be free
        CP_WAIT0();
        __syncthreads();
    }

    // ---- normalize, stage O^T ----
    l0 += __shfl_xor_sync(0xffffffffu, l0, 1);
    l0 += __shfl_xor_sync(0xffffffffu, l0, 2);
    l1 += __shfl_xor_sync(0xffffffffu, l1, 1);
    l1 += __shfl_xor_sync(0xffffffffu, l1, 2);
    const float inv0 = 1.0f / l0, inv1 = 1.0f / l1;

    float* smO = reinterpret_cast<float*>(smem);   // [256 c][72 n]
    const int rl = wr * 16 + gid;
    #pragma unroll
    for (int nt = 0; nt < 16; nt++) {
        const int c = wc * 128 + nt * 8 + tig * 2;
        smO[c * AOSTR + rl]           = oacc[nt][0] * inv0;
        smO[(c + 1) * AOSTR + rl]     = oacc[nt][1] * inv0;
        smO[c * AOSTR + rl + 8]       = oacc[nt][2] * inv1;
        smO[(c + 1) * AOSTR + rl + 8] = oacc[nt][3] * inv1;
    }
    __syncthreads();

    // ---- y = x + alpha * O^T (64 cols per row, float4) ----
    const float* xg = x + (size_t)b * CDIM * NPIX + m0;
    float*       yg = y + (size_t)b * CDIM * NPIX + m0;
    const int slot = tid & 15, rb = tid >> 4;
    #pragma unroll 4
    for (int t = 0; t < 16; t++) {
        const int cc = rb + t * 16;
        const float4 xv = *reinterpret_cast<const float4*>(xg + (size_t)cc * NPIX + slot * 4);
        const float4 ov = *reinterpret_cast<const float4*>(&smO[cc * AOSTR + slot * 4]);
        float4 r;
        r.x = fmaf(av, ov.x, xv.x);
        r.y = fmaf(av, ov.y, xv.y);
        r.z = fmaf(av, ov.z, xv.z);
        r.w = fmaf(av, ov.w, xv.w);
        *reinterpret_cast<float4*>(yg + (size_t)cc * NPIX + slot * 4) = r;
    }
}

// ===========================================================================
// Merged projection GEMM (one launch, 3-stage pipeline).
// gridDim.y = 6: (g = y>>1) 0:Q 1:K 2:V ; n0 = (y&1)*128.
// g<2: fp32 out [m][n];  g==2: bf16 transposed out [n][m].
// ===========================================================================
#define KCH     32
#define ROWB    80
#define TILEB   (128 * ROWB)
#define STAGEB  (2 * TILEB)
#define POSTR   136

__global__ void __launch_bounds__(256, 2)
proj_kernel(const __nv_bfloat16* __restrict__ xT, const __nv_bfloat16* __restrict__ tT,
            const __nv_bfloat16* __restrict__ Wqb, const __nv_bfloat16* __restrict__ Wkb,
            const __nv_bfloat16* __restrict__ Wvb,
            float* __restrict__ qf, float* __restrict__ kf, __nv_bfloat16* __restrict__ vTo)
{
    __shared__ __align__(128) unsigned char smem[3 * STAGEB];   // 61440

    const int tid  = threadIdx.x;
    const int lane = tid & 31;
    const int wid  = tid >> 5;
    const int b  = blockIdx.z;
    const int m0 = blockIdx.x * 128;
    const int g  = blockIdx.y >> 1;
    const int n0 = (blockIdx.y & 1) * 128;
    const int wm = (wid >> 2) * 64;
    const int wn = (wid & 3) * 32;

    const __nv_bfloat16* A;
    const __nv_bfloat16* B;
    int K;
    if (g == 0)      { A = xT; B = Wqb; K = CDIM; }
    else if (g == 1) { A = tT; B = Wkb; K = TCDIM; }
    else             { A = tT; B = Wvb; K = TCDIM; }

    const uint32_t sbase = smem_u32(smem);
    const __nv_bfloat16* Ab = A + ((size_t)b * NPIX + m0) * K;
    const __nv_bfloat16* Bb = B + (size_t)n0 * K;

    const int cr = tid >> 1;
    const int cs = tid & 1;

    float acc[4][4][4];
    #pragma unroll
    for (int i = 0; i < 4; i++)
        #pragma unroll
        for (int j = 0; j < 4; j++)
            #pragma unroll
            for (int e = 0; e < 4; e++) acc[i][j][e] = 0.f;

    const int nch = K / KCH;   // 8 or 16

    auto issue = [&](int ch, int buf) {
        const uint32_t sa  = sbase + buf * STAGEB + cr * ROWB;
        const uint32_t sbm = sa + TILEB;
        const __nv_bfloat16* ga = Ab + (size_t)cr * K + ch * KCH;
        const __nv_bfloat16* gb = Bb + (size_t)cr * K + ch * KCH;
        #pragma unroll
        for (int s = 0; s < 2; s++) {
            const int seg = cs + s * 2;
            CP_ASYNC16(sa + seg * 16, ga + seg * 8);
            CP_ASYNC16(sbm + seg * 16, gb + seg * 8);
        }
    };

    issue(0, 0); CP_COMMIT();
    issue(1, 1); CP_COMMIT();

    int buf = 0;
    for (int ch = 0; ch < nch; ch++) {
        if (ch + 2 < nch) {
            int nb = buf + 2; if (nb >= 3) nb -= 3;
            issue(ch + 2, nb); CP_COMMIT();
            CP_WAIT2();
        } else if (ch + 1 < nch) {
            CP_WAIT1();
        } else {
            CP_WAIT0();
        }
        __syncthreads();

        const uint32_t aT = sbase + buf * STAGEB;
        const uint32_t bT = aT + TILEB;
        #pragma unroll
        for (int ks = 0; ks < 2; ks++) {
            uint32_t af[4][4], bfr[4][2];
            const int akoff = (ks * 16 + (lane >> 4) * 8) * 2;
            const int arow  = wm + (lane & 15);
            #pragma unroll
            for (int i = 0; i < 4; i++)
                LDSM_X4(af[i][0], af[i][1], af[i][2], af[i][3],
                        aT + (arow + i * 16) * ROWB + akoff);
            const int bkoff = (ks * 16 + ((lane >> 3) & 1) * 8) * 2;
            const int brow  = wn + (lane & 7);
            #pragma unroll
            for (int j = 0; j < 4; j++)
                LDSM_X2(bfr[j][0], bfr[j][1], bT + (brow + j * 8) * ROWB + bkoff);
            #pragma unroll
            for (int i = 0; i < 4; i++)
                #pragma unroll
                for (int j = 0; j < 4; j++)
                    MMA16816(acc[i][j], af[i], bfr[j]);
        }
        __syncthreads();
        if (++buf == 3) buf = 0;
    }

    const int gid = lane >> 2, tig = lane & 3;
    if (g < 2) {
        float* outb = (g == 0 ? qf : kf) + (size_t)b * NPIX * CDIM;
        #pragma unroll
        for (int i = 0; i < 4; i++) {
            #pragma unroll
            for (int j = 0; j < 4; j++) {
                const int r0 = m0 + wm + i * 16 + gid;
                const int c  = n0 + wn + j * 8 + tig * 2;
                *reinterpret_cast<float2*>(outb + (size_t)r0 * CDIM + c) =
                    make_float2(acc[i][j][0], acc[i][j][1]);
                *reinterpret_cast<float2*>(outb + (size_t)(r0 + 8) * CDIM + c) =
                    make_float2(acc[i][j][2], acc[i][j][3]);
            }
        }
    } else {
        __nv_bfloat16* smB = reinterpret_cast<__nv_bfloat16*>(smem);  // [128 c][136 m]
        #pragma unroll
        for (int i = 0; i < 4; i++) {
            #pragma unroll
            for (int j = 0; j < 4; j++) {
                const int ml = wm + i * 16 + gid;
                const int cl = wn + j * 8 + tig * 2;
                smB[cl * POSTR + ml]           = __float2bfloat16(acc[i][j][0]);
                smB[(cl + 1) * POSTR + ml]     = __float2bfloat16(acc[i][j][1]);
                smB[cl * POSTR + ml + 8]       = __float2bfloat16(acc[i][j][2]);
                smB[(cl + 1) * POSTR + ml + 8] = __float2bfloat16(acc[i][j][3]);
            }
        }
        __syncthreads();
        __nv_bfloat16* og = vTo + (size_t)b * CDIM * NPIX;
        #pragma unroll
        for (int t = 0; t < 16; t++) {
            const int cl = wid + t * 8;
            const uint2 v = *reinterpret_cast<const uint2*>(&smB[cl * POSTR + lane * 4]);
            *reinterpret_cast<uint2*>(og + (size_t)(n0 + cl) * NPIX + m0 + lane * 4) = v;
        }
    }
}

// ===========================================================================
// merged transpose + bf16 convert for x (K=256) and token (K=512)
// ===========================================================================
__global__ void trans2_kernel(const float* __restrict__ x, const float* __restrict__ token,
                              __nv_bfloat16* __restrict__ xT, __nv_bfloat16* __restrict__ tT) {
    __shared__ float sm[64][33];
    const int b  = blockIdx.z;
    const bool isX = blockIdx.y < (CDIM / 64);
    const int K  = isX ? CDIM : TCDIM;
    const int k0 = (isX ? blockIdx.y : blockIdx.y - CDIM / 64) * 64;
    const float* in = isX ? x : token;
    __nv_bfloat16* out = isX ? xT : tT;
    const int n0 = blockIdx.x * 32;
    const int tx = threadIdx.x, ty = threadIdx.y;
    const float* ib = in + (size_t)b * K * NPIX;
    #pragma unroll
    for (int i = 0; i < 8; i++) {
        const int kk = ty + i * 8;
        sm[kk][tx] = ib[(size_t)(k0 + kk) * NPIX + n0 + tx];
    }
    __syncthreads();
    const int tid = ty * 32 + tx;
    const int n = tid >> 3, kg = tid & 7;
    __nv_bfloat16 v[8];
    #pragma unroll
    for (int j = 0; j < 8; j++) v[j] = __float2bfloat16(sm[kg * 8 + j][n]);
    __nv_bfloat16* ob = out + (size_t)b * NPIX * K;
    *reinterpret_cast<uint4*>(ob + (size_t)(n0 + n) * K + k0 + kg * 8) =
        *reinterpret_cast<const uint4*>(v);
}

__global__ void conv3_kernel(const float* __restrict__ Wq, const float* __restrict__ Wk,
                             const float* __restrict__ Wv,
                             __nv_bfloat16* __restrict__ Wqb, __nv_bfloat16* __restrict__ Wkb,
                             __nv_bfloat16* __restrict__ Wvb) {
    const int i = blockIdx.x * blockDim.x + threadIdx.x;
    const int NQ = CDIM * CDIM / 4, NK = CDIM * TCDIM / 4;
    const float* in;
    __nv_bfloat16* out;
    int idx;
    if (i < NQ)           { in = Wq; out = Wqb; idx = i; }
    else if (i < NQ + NK) { in = Wk; out = Wkb; idx = i - NQ; }
    else if (i < NQ + 2 * NK) { in = Wv; out = Wvb; idx = i - NQ - NK; }
    else return;
    const float4 f = reinterpret_cast<const float4*>(in)[idx];
    __nv_bfloat16 v[4] = {__float2bfloat16(f.x), __float2bfloat16(f.y),
                          __float2bfloat16(f.z), __float2bfloat16(f.w)};
    reinterpret_cast<uint2*>(out)[idx] = *reinterpret_cast<const uint2*>(v);
}

// ===========================================================================
// normalize q,k rows (C=256) -> e4m3; 1 warp per row
// ===========================================================================
__global__ void norm_kernel(const float* __restrict__ q, const float* __restrict__ k,
                            uint8_t* __restrict__ q8, uint8_t* __restrict__ k8) {
    const int lane = threadIdx.x & 31;
    const size_t row = (size_t)blockIdx.x * 8 + (threadIdx.x >> 5);
    const float4 q1 = *reinterpret_cast<const float4*>(q + row * CDIM + lane * 8);
    const float4 q2 = *reinterpret_cast<const float4*>(q + row * CDIM + lane * 8 + 4);
    const float4 k1 = *reinterpret_cast<const float4*>(k + row * CDIM + lane * 8);
    const float4 k2 = *reinterpret_cast<const float4*>(k + row * CDIM + lane * 8 + 4);
    float sq = q1.x*q1.x + q1.y*q1.y + q1.z*q1.z + q1.w*q1.w
             + q2.x*q2.x + q2.y*q2.y + q2.z*q2.z + q2.w*q2.w;
    float sk = k1.x*k1.x + k1.y*k1.y + k1.z*k1.z + k1.w*k1.w
             + k2.x*k2.x + k2.y*k2.y + k2.z*k2.z + k2.w*k2.w;
    #pragma unroll
    for (int o = 16; o > 0; o >>= 1) {
        sq += __shfl_xor_sync(0xffffffffu, sq, o);
        sk += __shfl_xor_sync(0xffffffffu, sk, o);
    }
    const float rq = 1.0f / fmaxf(sqrtf(sq), EPSN);
    const float rk = 1.0f / fmaxf(sqrtf(sk), EPSN);
    uint2 qp, kp;
    qp.x = pack_e4m3_4(q1.x*rq, q1.y*rq, q1.z*rq, q1.w*rq);
    qp.y = pack_e4m3_4(q2.x*rq, q2.y*rq, q2.z*rq, q2.w*rq);
    kp.x = pack_e4m3_4(k1.x*rk, k1.y*rk, k1.z*rk, k1.w*rk);
    kp.y = pack_e4m3_4(k2.x*rk, k2.y*rk, k2.z*rk, k2.w*rk);
    *reinterpret_cast<uint2*>(q8 + row * CDIM + lane * 8) = qp;
    *reinterpret_cast<uint2*>(k8 + row * CDIM + lane * 8) = kp;
}

// ===========================================================================
extern "C" void kernel_launch(void* const* d_in, const int* in_sizes, int n_in,
                              void* d_out, int out_size) {
    const float* x     = (const float*)d_in[0];
    const float* token = (const float*)d_in[1];
    const float* Wq    = (const float*)d_in[2];
    const float* Wk    = (const float*)d_in[3];
    const float* Wv    = (const float*)d_in[4];
    const float* alpha = (const float*)d_in[5];
    float* y = (float*)d_out;

    __nv_bfloat16 *xT, *tT, *Wqb, *Wkb, *Wvb, *vT;
    uint8_t *q8, *k8;
    float *qf, *kf;
    cudaGetSymbolAddress((void**)&xT,  g_xT);
    cudaGetSymbolAddress((void**)&tT,  g_tT);
    cudaGetSymbolAddress((void**)&Wqb, g_Wqb);
    cudaGetSymbolAddress((void**)&Wkb, g_Wkb);
    cudaGetSymbolAddress((void**)&Wvb, g_Wvb);
    cudaGetSymbolAddress((void**)&qf,  g_qf);
    cudaGetSymbolAddress((void**)&kf,  g_kf);
    cudaGetSymbolAddress((void**)&q8,  g_q8);
    cudaGetSymbolAddress((void**)&k8,  g_k8);
    cudaGetSymbolAddress((void**)&vT,  g_vT);

    cudaFuncSetAttribute(attn_kernel, cudaFuncAttributeMaxDynamicSharedMemorySize, SM_TOT);

    // 1) weight converts + input transposes
    {
        const int total = CDIM * CDIM / 4 + 2 * (CDIM * TCDIM / 4);
        conv3_kernel<<<(total + 255) / 256, 256>>>(Wq, Wk, Wv, Wqb, Wkb, Wvb);
        dim3 b1(32, 8);
        dim3 gt(NPIX / 32, CDIM / 64 + TCDIM / 64, BATCH);
        trans2_kernel<<<gt, b1>>>(x, token, xT, tT);
    }

    // 2) all three projections in ONE launch
    dim3 gp(NPIX / 128, 6, BATCH);            // 18 x 6 x 8 = 864 CTAs
    proj_kernel<<<gp, 256>>>(xT, tT, Wqb, Wkb, Wvb, qf, kf, vT);

    // 3) normalize q,k -> e4m3
    norm_kernel<<<BATCH * NPIX / 8, 256>>>(qf, kf, q8, k8);

    // 4) fused attention (BR=64, 2 CTAs/SM) + residual -> y
    dim3 ga(NPIX / BR, BATCH);                // 36 x 8 = 288 CTAs
    attn_kernel<<<ga, 256, SM_TOT>>>(q8, k8, vT, x, alpha, y);
}